// round 3
// baseline (speedup 1.0000x reference)
#include <cuda_runtime.h>
#include <cuda_bf16.h>
#include <math.h>

// Problem constants
#define CIN   32
#define COUT  32
#define KS    3
#define KVOL  27          // KS^3
#define DD    32
#define HH    64
#define WW    64
#define NVOX  (DD*HH*WW)  // 131072
#define NOFFCH 81         // 3*K
#define NMASKCH 27
#define NCONVCH 108       // 81 + 27

// Scratch (allocation-free rule: __device__ globals)
__device__ float g_offset[NOFFCH * NVOX];   // [ch][voxel], ch = dim*27 + k
__device__ float g_maskbuf[NMASKCH * NVOX]; // sigmoid already applied

// ---------------------------------------------------------------------------
// Kernel 1: fused conv producing offset (81 ch) and mask (27 ch, sigmoid).
// Block: one (d,h) row of 64 w positions, one group of 27 output channels.
// SMEM: x halo tile [32][3][3][66] (19008 f) + weights [27][864] (23328 f).
// Thread t: w = t&63, cq = t>>6 ; handles channels cq, cq+4, ... (<=7).
// ---------------------------------------------------------------------------
#define XS_ELEMS (CIN*3*3*66)   // 19008
#define WS1_ELEMS (27*864)      // 23328
#define SMEM1_BYTES ((XS_ELEMS + WS1_ELEMS)*4)

__global__ __launch_bounds__(256)
void conv_offmask(const float* __restrict__ x,
                  const float* __restrict__ w_off,
                  const float* __restrict__ b_off,
                  const float* __restrict__ w_mask,
                  const float* __restrict__ b_mask)
{
    extern __shared__ float sm[];
    float* xs = sm;               // [cin][dz][dy][66]
    float* ws = sm + XS_ELEMS;    // [ch_local][864]

    const int h   = blockIdx.x;
    const int d   = blockIdx.y;
    const int grp = blockIdx.z;   // 0..3, channels grp*27 .. grp*27+26
    const int tid = threadIdx.x;

    // Load x halo tile (zero-padded)
    for (int i = tid; i < XS_ELEMS; i += 256) {
        int cin = i / 594;            // 594 = 3*3*66
        int r   = i - cin*594;
        int dz  = r / 198;            // 198 = 3*66
        r      -= dz*198;
        int dy  = r / 66;
        int wx  = r - dy*66;
        int gd = d - 1 + dz, gh = h - 1 + dy, gw = wx - 1;
        float v = 0.f;
        if ((unsigned)gd < (unsigned)DD && (unsigned)gh < (unsigned)HH &&
            (unsigned)gw < (unsigned)WW)
            v = x[((cin*DD + gd)*HH + gh)*WW + gw];
        xs[i] = v;
    }
    // Load 27-channel weight slab (merged off/mask view)
    for (int i = tid; i < WS1_ELEMS; i += 256) {
        int cl   = i / 864;
        int rest = i - cl*864;
        int ch   = grp*27 + cl;
        ws[i] = (ch < NOFFCH) ? w_off[ch*864 + rest]
                              : w_mask[(ch - NOFFCH)*864 + rest];
    }
    __syncthreads();

    const int wpos = tid & 63;
    const int cq   = tid >> 6;       // 0..3

    float acc[7];
    #pragma unroll
    for (int j = 0; j < 7; j++) {
        int cl = cq + 4*j;
        float bv = 0.f;
        if (cl < 27) {
            int ch = grp*27 + cl;
            bv = (ch < NOFFCH) ? b_off[ch] : b_mask[ch - NOFFCH];
        }
        acc[j] = bv;
    }

    for (int cin = 0; cin < CIN; cin++) {
        #pragma unroll
        for (int kz = 0; kz < 3; kz++)
        #pragma unroll
        for (int ky = 0; ky < 3; ky++)
        #pragma unroll
        for (int kx = 0; kx < 3; kx++) {
            float xv = xs[((cin*3 + kz)*3 + ky)*66 + wpos + kx];
            int widx = cin*27 + kz*9 + ky*3 + kx;
            #pragma unroll
            for (int j = 0; j < 7; j++) {
                int cl = cq + 4*j;
                if (cl < 27)
                    acc[j] = fmaf(ws[cl*864 + widx], xv, acc[j]);
            }
        }
    }

    const int v = (d*HH + h)*WW + wpos;
    #pragma unroll
    for (int j = 0; j < 7; j++) {
        int cl = cq + 4*j;
        if (cl >= 27) break;
        int ch = grp*27 + cl;
        if (ch < NOFFCH) {
            g_offset[ch*NVOX + v] = acc[j];
        } else {
            float s = 1.f / (1.f + __expf(-acc[j]));
            g_maskbuf[(ch - NOFFCH)*NVOX + v] = s;
        }
    }
}

// ---------------------------------------------------------------------------
// Kernel 2: deformable sampling + (COUT x CIN*K) contraction.
// One thread per output voxel, acc[32] registers.
// Full weight tensor (32*32*27 = 27648 f = 110.6 KB) staged in SMEM.
// ---------------------------------------------------------------------------
#define WS2_ELEMS (COUT*CIN*KVOL)       // 27648
#define SMEM2_BYTES (WS2_ELEMS*4)

__global__ __launch_bounds__(128)
void deform_apply(const float* __restrict__ x,
                  const float* __restrict__ w,
                  const float* __restrict__ b,
                  float* __restrict__ out)
{
    extern __shared__ float ws[];   // [o][c*27 + k]
    const int tid = threadIdx.x;
    for (int i = tid; i < WS2_ELEMS; i += 128) ws[i] = w[i];
    __syncthreads();

    const int v  = blockIdx.x * 128 + tid;   // exactly covers 131072
    const int d  = v >> 12;                  // /4096
    const int h  = (v >> 6) & 63;
    const int wx = v & 63;

    float acc[COUT];
    #pragma unroll
    for (int o = 0; o < COUT; o++) acc[o] = 0.f;

    for (int k = 0; k < KVOL; k++) {
        const int kz = k / 9, ky = (k / 3) % 3, kx = k % 3;
        const float z  = (float)(d  - 1 + kz) + g_offset[(k      )*NVOX + v];
        const float y  = (float)(h  - 1 + ky) + g_offset[(27 + k )*NVOX + v];
        const float xc = (float)(wx - 1 + kx) + g_offset[(54 + k )*NVOX + v];
        const float m  = g_maskbuf[k*NVOX + v];

        const float z0f = floorf(z), y0f = floorf(y), x0f = floorf(xc);
        const float zf = z - z0f, yf = y - y0f, xf = xc - x0f;
        const int z0 = (int)z0f, y0 = (int)y0f, x0 = (int)x0f;

        int   idxs[8];
        float wgts[8];
        #pragma unroll
        for (int c8 = 0; c8 < 8; c8++) {
            int dz = c8 >> 2, dy = (c8 >> 1) & 1, dx = c8 & 1;
            int zi = z0 + dz, yi = y0 + dy, xi = x0 + dx;
            bool valid = (zi >= 0) && (zi < DD) && (yi >= 0) && (yi < HH) &&
                         (xi >= 0) && (xi < WW);
            float wg = (dz ? zf : 1.f - zf) * (dy ? yf : 1.f - yf)
                     * (dx ? xf : 1.f - xf);
            int zc = min(max(zi, 0), DD-1);
            int yc = min(max(yi, 0), HH-1);
            int xc2 = min(max(xi, 0), WW-1);
            idxs[c8] = (zc*HH + yc)*WW + xc2;
            wgts[c8] = valid ? wg : 0.f;
        }

        #pragma unroll 4
        for (int c = 0; c < CIN; c++) {
            const float* xb = x + c*NVOX;
            float s = 0.f;
            #pragma unroll
            for (int c8 = 0; c8 < 8; c8++)
                s = fmaf(wgts[c8], __ldg(xb + idxs[c8]), s);
            s *= m;
            const int wb = c*KVOL + k;
            #pragma unroll
            for (int o = 0; o < COUT; o++)
                acc[o] = fmaf(ws[o*864 + wb], s, acc[o]);
        }
    }

    #pragma unroll
    for (int o = 0; o < COUT; o++)
        out[o*NVOX + v] = acc[o] + b[o];
}

// ---------------------------------------------------------------------------
// Launch. Inputs (metadata order): x, w_off, b_off, w_mask, b_mask, w, b
// ---------------------------------------------------------------------------
extern "C" void kernel_launch(void* const* d_in, const int* in_sizes, int n_in,
                              void* d_out, int out_size)
{
    const float* x      = (const float*)d_in[0];
    const float* w_off  = (const float*)d_in[1];
    const float* b_off  = (const float*)d_in[2];
    const float* w_mask = (const float*)d_in[3];
    const float* b_mask = (const float*)d_in[4];
    const float* w      = (const float*)d_in[5];
    const float* b      = (const float*)d_in[6];
    float* out = (float*)d_out;

    cudaFuncSetAttribute(conv_offmask,
                         cudaFuncAttributeMaxDynamicSharedMemorySize, SMEM1_BYTES);
    cudaFuncSetAttribute(deform_apply,
                         cudaFuncAttributeMaxDynamicSharedMemorySize, SMEM2_BYTES);

    dim3 g1(HH, DD, 4);           // 64 x 32 x 4 channel groups
    conv_offmask<<<g1, 256, SMEM1_BYTES>>>(x, w_off, b_off, w_mask, b_mask);

    deform_apply<<<NVOX/128, 128, SMEM2_BYTES>>>(x, w, b, out);
}

// round 6
// speedup vs baseline: 1.7222x; 1.7222x over previous
#include <cuda_runtime.h>
#include <cuda_bf16.h>
#include <math.h>

// Problem constants
#define CIN   32
#define COUT  32
#define KS    3
#define KVOL  27
#define DD    32
#define HH    64
#define WW    64
#define NVOX  (DD*HH*WW)  // 131072
#define NOFFCH 81
#define NMASKCH 27
#define NCONVCH 108

// Scratch (__device__ globals; no allocation allowed)
__device__ float g_offset[NOFFCH * NVOX];    // [ch][v], ch = dim*27 + k
__device__ float g_maskbuf[NMASKCH * NVOX];  // sigmoid applied
__device__ float g_xt[NVOX * CIN];           // channel-last x: [v][c]
__device__ float g_wt[KVOL * CIN * COUT];    // [k][c][o]

// ---------------------------------------------------------------------------
// Transpose x: [c][v] -> [v][c]
// ---------------------------------------------------------------------------
__global__ void transpose_x(const float* __restrict__ x)
{
    __shared__ float t[32][33];
    const int v0 = blockIdx.x * 32;
    const int tx = threadIdx.x, ty = threadIdx.y;
    #pragma unroll
    for (int r = 0; r < 4; r++) {
        int c = ty + 8*r;
        t[c][tx] = x[c*NVOX + v0 + tx];
    }
    __syncthreads();
    #pragma unroll
    for (int r = 0; r < 4; r++) {
        int v = ty + 8*r;
        g_xt[(size_t)(v0 + v)*32 + tx] = t[tx][v];
    }
}

// Transpose w: [o][c][k] -> [k][c][o]
__global__ void transpose_w(const float* __restrict__ w)
{
    int i = blockIdx.x * 256 + threadIdx.x;   // 27648 total
    int k = i >> 10;
    int c = (i >> 5) & 31;
    int o = i & 31;
    g_wt[i] = w[(o*CIN + c)*KVOL + k];
}

// ---------------------------------------------------------------------------
// Kernel 1: offset/mask conv. Block = one (d,h) row x ALL 108 channels.
// Thread: 4 w-positions x 7 channels (cq + 16j). cin chunked by 4.
// Per (cin,kz,ky): 6 xs-LDS + 21 ws-LDS for 84 FMA -> FMA-bound.
// ---------------------------------------------------------------------------
#define CC 4
#define XSC_ELEMS (CC*3*3*66)        // 2376
#define WSC_ELEMS (NCONVCH*CC*KVOL)  // 11664
#define SMEMC_BYTES ((XSC_ELEMS + WSC_ELEMS)*4)

__global__ __launch_bounds__(256, 2)
void conv_offmask2(const float* __restrict__ x,
                   const float* __restrict__ w_off,
                   const float* __restrict__ b_off,
                   const float* __restrict__ w_mask,
                   const float* __restrict__ b_mask)
{
    extern __shared__ float sm[];
    float* xs = sm;                 // [CC][3][3][66]
    float* ws = sm + XSC_ELEMS;     // [108][CC*27]

    const int h   = blockIdx.x;
    const int d   = blockIdx.y;
    const int tid = threadIdx.x;
    const int wq  = tid & 15;       // w-quad: wpos = wq*4 + p
    const int cq  = tid >> 4;       // 0..15: channels cq + 16j

    float acc[7][4];
    #pragma unroll
    for (int j = 0; j < 7; j++) {
        int ch = cq + 16*j;
        float bv = 0.f;
        if (ch < NOFFCH)      bv = b_off[ch];
        else if (ch < NCONVCH) bv = b_mask[ch - NOFFCH];
        #pragma unroll
        for (int p = 0; p < 4; p++) acc[j][p] = bv;
    }

    for (int cc = 0; cc < CIN/CC; cc++) {
        if (cc) __syncthreads();
        // x halo chunk [CC][3][3][66], zero padded
        for (int i = tid; i < XSC_ELEMS; i += 256) {
            int ci = i / 594;
            int r  = i - ci*594;
            int dz = r / 198;  r -= dz*198;
            int dy = r / 66;
            int wx = r - dy*66;
            int cin = cc*CC + ci;
            int gd = d - 1 + dz, gh = h - 1 + dy, gw = wx - 1;
            float v = 0.f;
            if ((unsigned)gd < (unsigned)DD && (unsigned)gh < (unsigned)HH &&
                (unsigned)gw < (unsigned)WW)
                v = x[((cin*DD + gd)*HH + gh)*WW + gw];
            xs[i] = v;
        }
        // weight chunk [108][CC*27]
        for (int i = tid; i < WSC_ELEMS; i += 256) {
            int ch = i / (CC*KVOL);
            int r  = i - ch*(CC*KVOL);
            int ci = r / KVOL;
            int t  = r - ci*KVOL;
            int cin = cc*CC + ci;
            ws[i] = (ch < NOFFCH) ? w_off[(ch*CIN + cin)*KVOL + t]
                                  : w_mask[((ch - NOFFCH)*CIN + cin)*KVOL + t];
        }
        __syncthreads();

        #pragma unroll
        for (int ci = 0; ci < CC; ci++) {
            #pragma unroll
            for (int kz = 0; kz < 3; kz++)
            #pragma unroll
            for (int ky = 0; ky < 3; ky++) {
                float xv[6];
                #pragma unroll
                for (int u = 0; u < 6; u++)
                    xv[u] = xs[ci*594 + (kz*3 + ky)*66 + wq*4 + u];
                #pragma unroll
                for (int kx = 0; kx < 3; kx++) {
                    #pragma unroll
                    for (int j = 0; j < 7; j++) {
                        int ch = cq + 16*j;
                        if (ch < NCONVCH) {
                            float wv = ws[ch*(CC*KVOL) + ci*KVOL + kz*9 + ky*3 + kx];
                            #pragma unroll
                            for (int p = 0; p < 4; p++)
                                acc[j][p] = fmaf(wv, xv[p + kx], acc[j][p]);
                        }
                    }
                }
            }
        }
    }

    const int vbase = (d*HH + h)*WW + wq*4;
    #pragma unroll
    for (int j = 0; j < 7; j++) {
        int ch = cq + 16*j;
        if (ch >= NCONVCH) continue;
        #pragma unroll
        for (int p = 0; p < 4; p++) {
            float v = acc[j][p];
            if (ch < NOFFCH) {
                g_offset[(size_t)ch*NVOX + vbase + p] = v;
            } else {
                g_maskbuf[(size_t)(ch - NOFFCH)*NVOX + vbase + p] =
                    1.f / (1.f + __expf(-v));
            }
        }
    }
}

// ---------------------------------------------------------------------------
// Kernel 2: deformable sampling + contraction, per-tap two-phase.
// Block = 128 voxels, 256 threads.
// Phase A: sample val_s[c][v] (2 threads/voxel, 16 channels each, float4 gathers)
// Phase B: 32o x 32c x 128v register-tiled GEMM (4o x 4v per thread).
// ---------------------------------------------------------------------------
#define VB 128

__global__ __launch_bounds__(256, 2)
void deform2(const float* __restrict__ b, float* __restrict__ out)
{
    __shared__ float val_s[CIN][VB];      // 16 KB
    __shared__ float wk_s[CIN*COUT];      // 4 KB: wt slice [c][o] for tap k

    const int tid = threadIdx.x;
    const int v0  = blockIdx.x * VB;

    // Phase A role
    const int vi   = tid & 127;
    const int ch0  = (tid >> 7) * 16;     // 0 or 16
    const int v    = v0 + vi;
    const int dd   = v >> 12;
    const int hh   = (v >> 6) & 63;
    const int wxp  = v & 63;

    // Phase B role
    const int to = tid & 7;               // o0 = to*4
    const int tv = tid >> 3;              // vb = tv*4
    const int o0 = to * 4;
    const int vb = tv * 4;

    float4 a0 = {0,0,0,0}, a1 = {0,0,0,0}, a2 = {0,0,0,0}, a3 = {0,0,0,0};

    for (int k = 0; k < KVOL; k++) {
        if (k) __syncthreads();           // protect val_s/wk_s from prev phase B

        // weight slice for this tap: [c][o], coalesced
        #pragma unroll
        for (int i = 0; i < 4; i++)
            wk_s[tid + 256*i] = g_wt[k*1024 + tid + 256*i];

        // ---- Phase A: sampling ----
        const int kz = k / 9, ky = (k / 3) % 3, kx = k % 3;
        float z  = (float)(dd  - 1 + kz) + g_offset[(size_t)(k     )*NVOX + v];
        float y  = (float)(hh  - 1 + ky) + g_offset[(size_t)(27 + k)*NVOX + v];
        float xx = (float)(wxp - 1 + kx) + g_offset[(size_t)(54 + k)*NVOX + v];
        float m  = g_maskbuf[(size_t)k*NVOX + v];

        float z0f = floorf(z), y0f = floorf(y), x0f = floorf(xx);
        float zf = z - z0f, yf = y - y0f, xf = xx - x0f;
        int z0 = (int)z0f, y0 = (int)y0f, x0 = (int)x0f;

        float4 va0 = {0,0,0,0}, va1 = {0,0,0,0}, va2 = {0,0,0,0}, va3 = {0,0,0,0};
        #pragma unroll
        for (int c8 = 0; c8 < 8; c8++) {
            int dz = c8 >> 2, dy = (c8 >> 1) & 1, dx = c8 & 1;
            int zi = z0 + dz, yi = y0 + dy, xi = x0 + dx;
            bool valid = (unsigned)zi < (unsigned)DD &&
                         (unsigned)yi < (unsigned)HH &&
                         (unsigned)xi < (unsigned)WW;
            float wg = (dz ? zf : 1.f - zf) * (dy ? yf : 1.f - yf)
                     * (dx ? xf : 1.f - xf);
            if (valid && wg != 0.f) {
                const float4* xr = (const float4*)
                    (g_xt + ((size_t)((zi*HH + yi)*WW + xi))*32 + ch0);
                float4 t;
                t = xr[0];
                va0.x = fmaf(wg, t.x, va0.x); va0.y = fmaf(wg, t.y, va0.y);
                va0.z = fmaf(wg, t.z, va0.z); va0.w = fmaf(wg, t.w, va0.w);
                t = xr[1];
                va1.x = fmaf(wg, t.x, va1.x); va1.y = fmaf(wg, t.y, va1.y);
                va1.z = fmaf(wg, t.z, va1.z); va1.w = fmaf(wg, t.w, va1.w);
                t = xr[2];
                va2.x = fmaf(wg, t.x, va2.x); va2.y = fmaf(wg, t.y, va2.y);
                va2.z = fmaf(wg, t.z, va2.z); va2.w = fmaf(wg, t.w, va2.w);
                t = xr[3];
                va3.x = fmaf(wg, t.x, va3.x); va3.y = fmaf(wg, t.y, va3.y);
                va3.z = fmaf(wg, t.z, va3.z); va3.w = fmaf(wg, t.w, va3.w);
            }
        }
        val_s[ch0 +  0][vi] = va0.x * m;  val_s[ch0 +  1][vi] = va0.y * m;
        val_s[ch0 +  2][vi] = va0.z * m;  val_s[ch0 +  3][vi] = va0.w * m;
        val_s[ch0 +  4][vi] = va1.x * m;  val_s[ch0 +  5][vi] = va1.y * m;
        val_s[ch0 +  6][vi] = va1.z * m;  val_s[ch0 +  7][vi] = va1.w * m;
        val_s[ch0 +  8][vi] = va2.x * m;  val_s[ch0 +  9][vi] = va2.y * m;
        val_s[ch0 + 10][vi] = va2.z * m;  val_s[ch0 + 11][vi] = va2.w * m;
        val_s[ch0 + 12][vi] = va3.x * m;  val_s[ch0 + 13][vi] = va3.y * m;
        val_s[ch0 + 14][vi] = va3.z * m;  val_s[ch0 + 15][vi] = va3.w * m;

        __syncthreads();

        // ---- Phase B: 4o x 4v register tile over c ----
        #pragma unroll 8
        for (int c = 0; c < CIN; c++) {
            float4 wv  = *(const float4*)&wk_s[c*32 + o0];
            float4 xv4 = *(const float4*)&val_s[c][vb];
            a0.x = fmaf(wv.x, xv4.x, a0.x); a0.y = fmaf(wv.y, xv4.x, a0.y);
            a0.z = fmaf(wv.z, xv4.x, a0.z); a0.w = fmaf(wv.w, xv4.x, a0.w);
            a1.x = fmaf(wv.x, xv4.y, a1.x); a1.y = fmaf(wv.y, xv4.y, a1.y);
            a1.z = fmaf(wv.z, xv4.y, a1.z); a1.w = fmaf(wv.w, xv4.y, a1.w);
            a2.x = fmaf(wv.x, xv4.z, a2.x); a2.y = fmaf(wv.y, xv4.z, a2.y);
            a2.z = fmaf(wv.z, xv4.z, a2.z); a2.w = fmaf(wv.w, xv4.z, a2.w);
            a3.x = fmaf(wv.x, xv4.w, a3.x); a3.y = fmaf(wv.y, xv4.w, a3.y);
            a3.z = fmaf(wv.z, xv4.w, a3.z); a3.w = fmaf(wv.w, xv4.w, a3.w);
        }
    }

    // Write-out: thread covers o0..o0+3, voxels v0+vb..+3
    const int vg = v0 + vb;
    float bo0 = b[o0], bo1 = b[o0+1], bo2 = b[o0+2], bo3 = b[o0+3];
    out[(size_t)(o0+0)*NVOX + vg+0] = a0.x + bo0;
    out[(size_t)(o0+1)*NVOX + vg+0] = a0.y + bo1;
    out[(size_t)(o0+2)*NVOX + vg+0] = a0.z + bo2;
    out[(size_t)(o0+3)*NVOX + vg+0] = a0.w + bo3;
    out[(size_t)(o0+0)*NVOX + vg+1] = a1.x + bo0;
    out[(size_t)(o0+1)*NVOX + vg+1] = a1.y + bo1;
    out[(size_t)(o0+2)*NVOX + vg+1] = a1.z + bo2;
    out[(size_t)(o0+3)*NVOX + vg+1] = a1.w + bo3;
    out[(size_t)(o0+0)*NVOX + vg+2] = a2.x + bo0;
    out[(size_t)(o0+1)*NVOX + vg+2] = a2.y + bo1;
    out[(size_t)(o0+2)*NVOX + vg+2] = a2.z + bo2;
    out[(size_t)(o0+3)*NVOX + vg+2] = a2.w + bo3;
    out[(size_t)(o0+0)*NVOX + vg+3] = a3.x + bo0;
    out[(size_t)(o0+1)*NVOX + vg+3] = a3.y + bo1;
    out[(size_t)(o0+2)*NVOX + vg+3] = a3.z + bo2;
    out[(size_t)(o0+3)*NVOX + vg+3] = a3.w + bo3;
}

// ---------------------------------------------------------------------------
// Launch. Inputs: x, w_off, b_off, w_mask, b_mask, w, b
// ---------------------------------------------------------------------------
extern "C" void kernel_launch(void* const* d_in, const int* in_sizes, int n_in,
                              void* d_out, int out_size)
{
    const float* x      = (const float*)d_in[0];
    const float* w_off  = (const float*)d_in[1];
    const float* b_off  = (const float*)d_in[2];
    const float* w_mask = (const float*)d_in[3];
    const float* b_mask = (const float*)d_in[4];
    const float* w      = (const float*)d_in[5];
    const float* b      = (const float*)d_in[6];
    float* out = (float*)d_out;

    cudaFuncSetAttribute(conv_offmask2,
                         cudaFuncAttributeMaxDynamicSharedMemorySize, SMEMC_BYTES);

    transpose_w<<<(KVOL*CIN*COUT)/256, 256>>>(w);
    transpose_x<<<NVOX/32, dim3(32, 8)>>>(x);

    dim3 gc(HH, DD);
    conv_offmask2<<<gc, 256, SMEMC_BYTES>>>(x, w_off, b_off, w_mask, b_mask);

    deform2<<<NVOX/VB, 256>>>(b, out);
}

// round 7
// speedup vs baseline: 2.6566x; 1.5425x over previous
#include <cuda_runtime.h>
#include <cuda_bf16.h>
#include <math.h>

// Problem constants
#define CIN   32
#define COUT  32
#define KVOL  27
#define DD    32
#define HH    64
#define WW    64
#define NVOX  (DD*HH*WW)  // 131072
#define NOFFCH 81
#define NMASKCH 27
#define NCONVCH 108

typedef unsigned long long ull;

// Scratch (__device__ globals; no allocation allowed)
__device__ float  g_offset[NOFFCH * NVOX];    // [ch][v]
__device__ float  g_maskbuf[NMASKCH * NVOX];  // sigmoid applied
__device__ float  g_xt[NVOX * CIN];           // channel-last x: [v][c]
__device__ float  g_wt[KVOL * CIN * COUT];    // [k][c][o]
__device__ float2 g_wpair[8 * 48 * 4 * 27];   // [cc][jp*16+cq][ci][t] paired conv weights
__device__ float  g_w6[8 * 12 * 4 * 27];      // [cc][cq][ci][t] leftover channel group

// ---- f32x2 packed-FMA helpers (SASS FFMA2; only reachable via PTX) ----
__device__ __forceinline__ void fma2(ull& acc, ull a, ull b) {
    asm("fma.rn.f32x2 %0, %1, %2, %0;" : "+l"(acc) : "l"(a), "l"(b));
}
__device__ __forceinline__ ull pack2(float lo, float hi) {
    ull r; asm("mov.b64 %0, {%1, %2};" : "=l"(r) : "f"(lo), "f"(hi)); return r;
}
__device__ __forceinline__ void unpack2(ull v, float& lo, float& hi) {
    asm("mov.b64 {%0, %1}, %2;" : "=f"(lo), "=f"(hi) : "l"(v));
}

// ---------------------------------------------------------------------------
// Transpose x: [c][v] -> [v][c]
// ---------------------------------------------------------------------------
__global__ void transpose_x(const float* __restrict__ x)
{
    __shared__ float t[32][33];
    const int v0 = blockIdx.x * 32;
    const int tx = threadIdx.x, ty = threadIdx.y;
    #pragma unroll
    for (int r = 0; r < 4; r++) {
        int c = ty + 8*r;
        t[c][tx] = x[c*NVOX + v0 + tx];
    }
    __syncthreads();
    #pragma unroll
    for (int r = 0; r < 4; r++) {
        int v = ty + 8*r;
        g_xt[(size_t)(v0 + v)*32 + tx] = t[tx][v];
    }
}

// Transpose w: [o][c][k] -> [k][c][o]
__global__ void transpose_w(const float* __restrict__ w)
{
    int i = blockIdx.x * 256 + threadIdx.x;
    int k = i >> 10;
    int c = (i >> 5) & 31;
    int o = i & 31;
    g_wt[i] = w[(o*CIN + c)*KVOL + k];
}

// Pre-pair conv weights: pairs (ch, ch+16) for ch = cq + 32*jp, plus group 6.
__global__ void prep_wconv(const float* __restrict__ w_off,
                           const float* __restrict__ w_mask)
{
    int i = blockIdx.x * 256 + threadIdx.x;
    if (i < 8*48*4*27) {
        int t   = i % 27;
        int r   = i / 27;
        int ci  = r & 3;
        int row = (r >> 2) % 48;
        int cc  = r / 192;
        int cin = cc*4 + ci;
        int jp  = row >> 4, cq = row & 15;
        int ch1 = cq + 32*jp, ch2 = ch1 + 16;
        float a = (ch1 < NOFFCH) ? w_off[(ch1*CIN + cin)*KVOL + t]
                                 : w_mask[((ch1 - NOFFCH)*CIN + cin)*KVOL + t];
        float b = (ch2 < NOFFCH) ? w_off[(ch2*CIN + cin)*KVOL + t]
                                 : w_mask[((ch2 - NOFFCH)*CIN + cin)*KVOL + t];
        g_wpair[i] = make_float2(a, b);
    }
    if (i < 8*12*4*27) {
        int t  = i % 27;
        int r  = i / 27;
        int ci = r & 3;
        int cq = (r >> 2) % 12;
        int cc = r / 48;
        int cin = cc*4 + ci;
        int ch  = cq + 96;                       // 96..107, always mask
        g_w6[i] = w_mask[((ch - NOFFCH)*CIN + cin)*KVOL + t];
    }
}

// ---------------------------------------------------------------------------
// Kernel 1: offset/mask conv with packed FFMA2.
// Block = one (d,h) row x all 108 channels; thread = 4 w-positions x 7 ch.
// Channel pairs (cq+32jp, cq+32jp+16) share one b64 accumulator per position.
// ---------------------------------------------------------------------------
#define CC 4
#define XSC_ELEMS (CC*3*3*66)           // 2376 floats
#define WSP_ELEMS (48*CC*KVOL)          // 5184 float2
#define WS6_ELEMS (12*CC*KVOL)          // 1296 floats
#define SMEMC_BYTES (XSC_ELEMS*4 + WSP_ELEMS*8 + WS6_ELEMS*4)

__global__ __launch_bounds__(256, 2)
void conv_offmask3(const float* __restrict__ x,
                   const float* __restrict__ b_off,
                   const float* __restrict__ b_mask)
{
    extern __shared__ float sm[];
    float*  xs  = sm;                                  // [CC][3][3][66]
    float2* wsp = (float2*)(sm + XSC_ELEMS);           // [48][CC*27]
    float*  ws6 = sm + XSC_ELEMS + WSP_ELEMS*2;        // [12][CC*27]

    const int h   = blockIdx.x;
    const int d   = blockIdx.y;
    const int tid = threadIdx.x;
    const int wq  = tid & 15;        // w-quad: wpos = wq*4 + p
    const int cq  = tid >> 4;        // 0..15

    ull acc2[3][4];
    float acc6[4];
    #pragma unroll
    for (int jp = 0; jp < 3; jp++) {
        int ch1 = cq + 32*jp, ch2 = ch1 + 16;
        float b1 = (ch1 < NOFFCH) ? b_off[ch1] : b_mask[ch1 - NOFFCH];
        float b2 = (ch2 < NOFFCH) ? b_off[ch2] : b_mask[ch2 - NOFFCH];
        ull bp = pack2(b1, b2);
        #pragma unroll
        for (int p = 0; p < 4; p++) acc2[jp][p] = bp;
    }
    {
        float b6 = (cq < 12) ? b_mask[cq + 96 - NOFFCH] : 0.f;
        #pragma unroll
        for (int p = 0; p < 4; p++) acc6[p] = b6;
    }

    for (int cc = 0; cc < CIN/CC; cc++) {
        if (cc) __syncthreads();
        // x halo chunk [CC][3][3][66], zero padded
        for (int i = tid; i < XSC_ELEMS; i += 256) {
            int ci = i / 594;
            int r  = i - ci*594;
            int dz = r / 198;  r -= dz*198;
            int dy = r / 66;
            int wx = r - dy*66;
            int cin = cc*CC + ci;
            int gd = d - 1 + dz, gh = h - 1 + dy, gw = wx - 1;
            float v = 0.f;
            if ((unsigned)gd < (unsigned)DD && (unsigned)gh < (unsigned)HH &&
                (unsigned)gw < (unsigned)WW)
                v = x[((cin*DD + gd)*HH + gh)*WW + gw];
            xs[i] = v;
        }
        // paired weight chunks (coalesced copies of pre-transposed slabs)
        {
            const float2* src = g_wpair + cc*WSP_ELEMS;
            for (int i = tid; i < WSP_ELEMS; i += 256) wsp[i] = src[i];
            const float* s6 = g_w6 + cc*WS6_ELEMS;
            for (int i = tid; i < WS6_ELEMS; i += 256) ws6[i] = s6[i];
        }
        __syncthreads();

        #pragma unroll
        for (int ci = 0; ci < CC; ci++) {
            #pragma unroll
            for (int kz = 0; kz < 3; kz++)
            #pragma unroll
            for (int ky = 0; ky < 3; ky++) {
                float xv[6];
                ull   xd[6];
                #pragma unroll
                for (int u = 0; u < 6; u++) {
                    xv[u] = xs[ci*594 + (kz*3 + ky)*66 + wq*4 + u];
                    xd[u] = pack2(xv[u], xv[u]);
                }
                #pragma unroll
                for (int kx = 0; kx < 3; kx++) {
                    const int t = ci*KVOL + kz*9 + ky*3 + kx;
                    #pragma unroll
                    for (int jp = 0; jp < 3; jp++) {
                        ull w2 = *(const ull*)&wsp[(jp*16 + cq)*(CC*KVOL) + t];
                        fma2(acc2[jp][0], w2, xd[kx + 0]);
                        fma2(acc2[jp][1], w2, xd[kx + 1]);
                        fma2(acc2[jp][2], w2, xd[kx + 2]);
                        fma2(acc2[jp][3], w2, xd[kx + 3]);
                    }
                    if (cq < 12) {
                        float w6 = ws6[cq*(CC*KVOL) + t];
                        #pragma unroll
                        for (int p = 0; p < 4; p++)
                            acc6[p] = fmaf(w6, xv[kx + p], acc6[p]);
                    }
                }
            }
        }
    }

    const int vbase = (d*HH + h)*WW + wq*4;
    #pragma unroll
    for (int jp = 0; jp < 3; jp++) {
        int ch1 = cq + 32*jp, ch2 = ch1 + 16;   // ch1 <= 79: always offset
        #pragma unroll
        for (int p = 0; p < 4; p++) {
            float lo, hi;
            unpack2(acc2[jp][p], lo, hi);
            g_offset[(size_t)ch1*NVOX + vbase + p] = lo;
            if (ch2 < NOFFCH)
                g_offset[(size_t)ch2*NVOX + vbase + p] = hi;
            else
                g_maskbuf[(size_t)(ch2 - NOFFCH)*NVOX + vbase + p] =
                    1.f / (1.f + __expf(-hi));
        }
    }
    if (cq < 12) {
        #pragma unroll
        for (int p = 0; p < 4; p++)
            g_maskbuf[(size_t)(cq + 96 - NOFFCH)*NVOX + vbase + p] =
                1.f / (1.f + __expf(-acc6[p]));
    }
}

// ---------------------------------------------------------------------------
// Kernel 2: deformable sampling + contraction.
// Phase A: lane = channel. Warp owns 16 voxels, processed in 4 groups of 4;
//   lane (j2 = lane>>3, c8 = lane&7) computes corner (idx, wgt*mask) for
//   voxel j2 -> smem; gather loop then does coalesced 128B line loads.
// Phase B: 32o x 32c x 128v tiled GEMM with packed FFMA2.
// ---------------------------------------------------------------------------
#define VB 128
#define VSP 36   // val_s row stride (floats): %4==0 for LDS.128, odd/4 banks ok

__global__ __launch_bounds__(256)
void deform3(const float* __restrict__ b, float* __restrict__ out)
{
    __shared__ float  val_s[VB][VSP];     // [voxel][channel] 18.4 KB
    __shared__ float  wk_s[CIN*COUT];     // [c][o] slice for tap k, 4 KB
    __shared__ float2 cs[8][32];          // per-warp corner (idx, wgt) 2 KB

    const int tid  = threadIdx.x;
    const int v0   = blockIdx.x * VB;
    const int warp = tid >> 5;
    const int lane = tid & 31;
    const int j2   = lane >> 3;          // voxel-in-group
    const int c8   = lane & 7;           // corner
    const int dz   = c8 >> 2, dy = (c8 >> 1) & 1, dxb = c8 & 1;

    // Phase B role
    const int o0 = (tid & 7) * 4;
    const int vb = (tid >> 3) * 4;

    ull aL[4], aH[4];
    #pragma unroll
    for (int i = 0; i < 4; i++) { aL[i] = pack2(0.f, 0.f); aH[i] = pack2(0.f, 0.f); }

    #pragma unroll 1
    for (int k = 0; k < KVOL; k++) {
        __syncthreads();                 // val_s/wk_s free from previous phase B

        // weight slice for this tap: [c][o]
        #pragma unroll
        for (int i = 0; i < 4; i++)
            wk_s[tid + 256*i] = g_wt[k*1024 + tid + 256*i];

        // ---- Phase A ----
        const int kz = k / 9, ky = (k / 3) % 3, kx = k % 3;
        #pragma unroll 1
        for (int g = 0; g < 4; g++) {
            const int viL = warp*16 + g*4 + j2;
            const int v   = v0 + viL;
            const int ddv = v >> 12, hhv = (v >> 6) & 63, wxp = v & 63;

            float z  = (float)(ddv - 1 + kz) + g_offset[(size_t)(k     )*NVOX + v];
            float y  = (float)(hhv - 1 + ky) + g_offset[(size_t)(27 + k)*NVOX + v];
            float xx = (float)(wxp - 1 + kx) + g_offset[(size_t)(54 + k)*NVOX + v];
            float m  = g_maskbuf[(size_t)k*NVOX + v];

            float z0f = floorf(z), y0f = floorf(y), x0f = floorf(xx);
            float zf = z - z0f, yf = y - y0f, xf = xx - x0f;
            int zi = (int)z0f + dz, yi = (int)y0f + dy, xi = (int)x0f + dxb;
            bool valid = (unsigned)zi < (unsigned)DD &&
                         (unsigned)yi < (unsigned)HH &&
                         (unsigned)xi < (unsigned)WW;
            float wg = (dz ? zf : 1.f - zf) * (dy ? yf : 1.f - yf)
                     * (dxb ? xf : 1.f - xf) * m;
            if (!valid) wg = 0.f;
            int zc = min(max(zi, 0), DD-1);
            int yc = min(max(yi, 0), HH-1);
            int xc = min(max(xi, 0), WW-1);
            int idx = (zc*HH + yc)*WW + xc;

            cs[warp][lane] = make_float2(__int_as_float(idx), wg);
            __syncwarp();

            float av[4] = {0.f, 0.f, 0.f, 0.f};
            #pragma unroll
            for (int jj = 0; jj < 4; jj++) {
                #pragma unroll
                for (int cc = 0; cc < 8; cc++) {
                    float2 cd = cs[warp][jj*8 + cc];
                    if (cd.y != 0.f)
                        av[jj] = fmaf(cd.y,
                                      g_xt[(size_t)__float_as_int(cd.x)*32 + lane],
                                      av[jj]);
                }
            }
            __syncwarp();
            #pragma unroll
            for (int jj = 0; jj < 4; jj++)
                val_s[warp*16 + g*4 + jj][lane] = av[jj];
        }

        __syncthreads();

        // ---- Phase B: FFMA2-packed 4o x 4v tile over c ----
        #pragma unroll
        for (int c0 = 0; c0 < 8; c0++) {
            float4 xi0 = *(const float4*)&val_s[vb + 0][c0*4];
            float4 xi1 = *(const float4*)&val_s[vb + 1][c0*4];
            float4 xi2 = *(const float4*)&val_s[vb + 2][c0*4];
            float4 xi3 = *(const float4*)&val_s[vb + 3][c0*4];
            #pragma unroll
            for (int cc = 0; cc < 4; cc++) {
                const int c = c0*4 + cc;
                ull wL = *(const ull*)&wk_s[c*32 + o0];
                ull wH = *(const ull*)&wk_s[c*32 + o0 + 2];
                float x0 = (&xi0.x)[cc], x1 = (&xi1.x)[cc];
                float x2 = (&xi2.x)[cc], x3 = (&xi3.x)[cc];
                ull xb0 = pack2(x0, x0);
                ull xb1 = pack2(x1, x1);
                ull xb2 = pack2(x2, x2);
                ull xb3 = pack2(x3, x3);
                fma2(aL[0], wL, xb0); fma2(aH[0], wH, xb0);
                fma2(aL[1], wL, xb1); fma2(aH[1], wH, xb1);
                fma2(aL[2], wL, xb2); fma2(aH[2], wH, xb2);
                fma2(aL[3], wL, xb3); fma2(aH[3], wH, xb3);
            }
        }
    }

    // Write-out
    const int vg = v0 + vb;
    float b0 = b[o0], b1 = b[o0+1], b2 = b[o0+2], b3 = b[o0+3];
    #pragma unroll
    for (int i = 0; i < 4; i++) {
        float lo, hi;
        unpack2(aL[i], lo, hi);
        out[(size_t)(o0+0)*NVOX + vg + i] = lo + b0;
        out[(size_t)(o0+1)*NVOX + vg + i] = hi + b1;
        unpack2(aH[i], lo, hi);
        out[(size_t)(o0+2)*NVOX + vg + i] = lo + b2;
        out[(size_t)(o0+3)*NVOX + vg + i] = hi + b3;
    }
}

// ---------------------------------------------------------------------------
// Launch. Inputs: x, w_off, b_off, w_mask, b_mask, w, b
// ---------------------------------------------------------------------------
extern "C" void kernel_launch(void* const* d_in, const int* in_sizes, int n_in,
                              void* d_out, int out_size)
{
    const float* x      = (const float*)d_in[0];
    const float* w_off  = (const float*)d_in[1];
    const float* b_off  = (const float*)d_in[2];
    const float* w_mask = (const float*)d_in[3];
    const float* b_mask = (const float*)d_in[4];
    const float* w      = (const float*)d_in[5];
    const float* b      = (const float*)d_in[6];
    float* out = (float*)d_out;

    cudaFuncSetAttribute(conv_offmask3,
                         cudaFuncAttributeMaxDynamicSharedMemorySize, SMEMC_BYTES);

    prep_wconv<<<(8*48*4*27 + 255)/256, 256>>>(w_off, w_mask);
    transpose_w<<<(KVOL*CIN*COUT)/256, 256>>>(w);
    transpose_x<<<NVOX/32, dim3(32, 8)>>>(x);

    dim3 gc(HH, DD);
    conv_offmask3<<<gc, 256, SMEMC_BYTES>>>(x, b_off, b_mask);

    deform3<<<NVOX/VB, 256>>>(b, out);
}

// round 9
// speedup vs baseline: 2.9369x; 1.1055x over previous
#include <cuda_runtime.h>
#include <cuda_bf16.h>
#include <math.h>

// Problem constants
#define CIN   32
#define COUT  32
#define KVOL  27
#define DD    32
#define HH    64
#define WW    64
#define NVOX  (DD*HH*WW)  // 131072
#define NOFFCH 81
#define NMASKCH 27
#define NCONVCH 108

typedef unsigned long long ull;

// Scratch (__device__ globals; no allocation allowed)
__device__ float  g_offset[NOFFCH * NVOX];    // [ch][v]
__device__ float  g_maskbuf[NMASKCH * NVOX];  // sigmoid applied
__device__ float  g_xt[NVOX * CIN];           // channel-last x: [v][c]
__device__ float  g_wt[KVOL * CIN * COUT];    // [k][c][o]
// conv weights, pre-fused for vector LDS:
//   quad : pairs (cq,cq+16) and (cq+32,cq+48)   -> float4
//   pair2: pair  (cq+64,cq+80)                  -> float2
//   w6   : leftover channels 96..107            -> float
#define CC 2
__device__ float4 g_wquad[16 * 16 * CC * KVOL];   // [cc][cq][ci][t]
__device__ float2 g_wpair2[16 * 16 * CC * KVOL];
__device__ float  g_w6[16 * 12 * CC * KVOL];

// ---- f32x2 packed-FMA helpers (SASS FFMA2; only reachable via PTX) ----
__device__ __forceinline__ void fma2(ull& acc, ull a, ull b) {
    asm("fma.rn.f32x2 %0, %1, %2, %0;" : "+l"(acc) : "l"(a), "l"(b));
}
__device__ __forceinline__ ull pack2(float lo, float hi) {
    ull r; asm("mov.b64 %0, {%1, %2};" : "=l"(r) : "f"(lo), "f"(hi)); return r;
}
__device__ __forceinline__ void unpack2(ull v, float& lo, float& hi) {
    asm("mov.b64 {%0, %1}, %2;" : "=f"(lo), "=f"(hi) : "l"(v));
}

// ---------------------------------------------------------------------------
// Transpose x: [c][v] -> [v][c]
// ---------------------------------------------------------------------------
__global__ void transpose_x(const float* __restrict__ x)
{
    __shared__ float t[32][33];
    const int v0 = blockIdx.x * 32;
    const int tx = threadIdx.x, ty = threadIdx.y;
    #pragma unroll
    for (int r = 0; r < 4; r++) {
        int c = ty + 8*r;
        t[c][tx] = x[c*NVOX + v0 + tx];
    }
    __syncthreads();
    #pragma unroll
    for (int r = 0; r < 4; r++) {
        int v = ty + 8*r;
        g_xt[(size_t)(v0 + v)*32 + tx] = t[tx][v];
    }
}

// Transpose w: [o][c][k] -> [k][c][o]
__global__ void transpose_w(const float* __restrict__ w)
{
    int i = blockIdx.x * 256 + threadIdx.x;
    int k = i >> 10;
    int c = (i >> 5) & 31;
    int o = i & 31;
    g_wt[i] = w[(o*CIN + c)*KVOL + k];
}

// Build fused conv-weight slabs.
__global__ void prep_wconv(const float* __restrict__ w_off,
                           const float* __restrict__ w_mask)
{
    int i = blockIdx.x * 256 + threadIdx.x;
    if (i < 16*16*CC*KVOL) {
        int t  = i % 27;
        int r  = i / 27;
        int ci = r & 1;  r >>= 1;
        int cq = r & 15;
        int cc = r >> 4;
        int cin = cc*CC + ci;
        auto W = [&](int ch) -> float {
            return (ch < NOFFCH) ? w_off[(ch*CIN + cin)*KVOL + t]
                                 : w_mask[((ch - NOFFCH)*CIN + cin)*KVOL + t];
        };
        g_wquad[i]  = make_float4(W(cq), W(cq+16), W(cq+32), W(cq+48));
        g_wpair2[i] = make_float2(W(cq+64), W(cq+80));
    }
    if (i < 16*12*CC*KVOL) {
        int t  = i % 27;
        int r  = i / 27;
        int ci = r & 1;  r >>= 1;
        int cq = r % 12;
        int cc = r / 12;
        int cin = cc*CC + ci;
        g_w6[i] = w_mask[((96 + cq - NOFFCH)*CIN + cin)*KVOL + t];
    }
}

// ---------------------------------------------------------------------------
// Kernel 1: offset/mask conv, FFMA2 + vector LDS, cin chunked by 2.
// Block = one (d,h) row x all 108 channels; thread = 4 w-positions x 7 ch.
// ---------------------------------------------------------------------------
#define XS_STRIDE 68                       // padded row (16B aligned)
#define XSC_ELEMS (CC*3*3*XS_STRIDE)       // 1224 floats
#define WQ_ELEMS  (16*CC*KVOL)             // 864 per chunk
#define W6_ELEMS  (12*CC*KVOL)             // 648 per chunk
#define SMEMC_BYTES (WQ_ELEMS*16 + WQ_ELEMS*8 + XSC_ELEMS*4 + W6_ELEMS*4)

__global__ __launch_bounds__(256, 3)
void conv_offmask4(const float* __restrict__ x,
                   const float* __restrict__ b_off,
                   const float* __restrict__ b_mask)
{
    extern __shared__ float sm[];
    float4* wq4 = (float4*)sm;                        // [cq][ci][t]
    float2* wp2 = (float2*)(sm + WQ_ELEMS*4);         // [cq][ci][t]
    float*  xs  = sm + WQ_ELEMS*6;                    // [ci][3][3][68]
    float*  ws6 = xs + XSC_ELEMS;                     // [cq12][ci][t]

    const int h   = blockIdx.x;
    const int d   = blockIdx.y;
    const int tid = threadIdx.x;
    const int wq  = tid & 15;        // wpos = wq*4 + p
    const int cq  = tid >> 4;        // 0..15

    ull acc2[3][4];
    float acc6[4];
    #pragma unroll
    for (int jp = 0; jp < 3; jp++) {
        int ch1 = cq + 32*jp, ch2 = ch1 + 16;
        float b1 = (ch1 < NOFFCH) ? b_off[ch1] : b_mask[ch1 - NOFFCH];
        float b2 = (ch2 < NOFFCH) ? b_off[ch2] : b_mask[ch2 - NOFFCH];
        ull bp = pack2(b1, b2);
        #pragma unroll
        for (int p = 0; p < 4; p++) acc2[jp][p] = bp;
    }
    {
        float b6 = (cq < 12) ? b_mask[cq + 96 - NOFFCH] : 0.f;
        #pragma unroll
        for (int p = 0; p < 4; p++) acc6[p] = b6;
    }

    #pragma unroll 1
    for (int cc = 0; cc < CIN/CC; cc++) {
        if (cc) __syncthreads();
        // x halo chunk [CC][3][3][68], zero padded
        for (int i = tid; i < XSC_ELEMS; i += 256) {
            int ci = i / (9*XS_STRIDE);
            int r  = i - ci*(9*XS_STRIDE);
            int dz = r / (3*XS_STRIDE);  r -= dz*(3*XS_STRIDE);
            int dy = r / XS_STRIDE;
            int wx = r - dy*XS_STRIDE;
            int cin = cc*CC + ci;
            int gd = d - 1 + dz, gh = h - 1 + dy, gw = wx - 1;
            float v = 0.f;
            if (wx < 66 && (unsigned)gd < (unsigned)DD &&
                (unsigned)gh < (unsigned)HH && (unsigned)gw < (unsigned)WW)
                v = x[((cin*DD + gd)*HH + gh)*WW + gw];
            xs[i] = v;
        }
        // weight chunks (coalesced)
        {
            const float4* sq = g_wquad  + cc*WQ_ELEMS;
            const float2* sp = g_wpair2 + cc*WQ_ELEMS;
            for (int i = tid; i < WQ_ELEMS; i += 256) { wq4[i] = sq[i]; wp2[i] = sp[i]; }
            const float* s6 = g_w6 + cc*W6_ELEMS;
            for (int i = tid; i < W6_ELEMS; i += 256) ws6[i] = s6[i];
        }
        __syncthreads();

        #pragma unroll
        for (int ci = 0; ci < CC; ci++) {
            #pragma unroll
            for (int kz = 0; kz < 3; kz++)
            #pragma unroll
            for (int ky = 0; ky < 3; ky++) {
                const float* xrow = &xs[ci*(9*XS_STRIDE) + (kz*3 + ky)*XS_STRIDE + wq*4];
                float4 xa = *(const float4*)xrow;
                float2 xb = *(const float2*)(xrow + 4);
                float xv[6] = {xa.x, xa.y, xa.z, xa.w, xb.x, xb.y};
                ull xd[6];
                #pragma unroll
                for (int u = 0; u < 6; u++) xd[u] = pack2(xv[u], xv[u]);

                #pragma unroll
                for (int kx = 0; kx < 3; kx++) {
                    const int t = (cq*CC + ci)*KVOL + kz*9 + ky*3 + kx;
                    ulonglong2 wv = *(const ulonglong2*)&wq4[t];
                    ull        w2 = *(const ull*)&wp2[t];
                    #pragma unroll
                    for (int p = 0; p < 4; p++) {
                        fma2(acc2[0][p], wv.x, xd[kx + p]);
                        fma2(acc2[1][p], wv.y, xd[kx + p]);
                        fma2(acc2[2][p], w2,   xd[kx + p]);
                    }
                    if (cq < 12) {
                        float w6v = ws6[(cq*CC + ci)*KVOL + kz*9 + ky*3 + kx];
                        #pragma unroll
                        for (int p = 0; p < 4; p++)
                            acc6[p] = fmaf(w6v, xv[kx + p], acc6[p]);
                    }
                }
            }
        }
    }

    const int vbase = (d*HH + h)*WW + wq*4;
    #pragma unroll
    for (int jp = 0; jp < 3; jp++) {
        int ch1 = cq + 32*jp, ch2 = ch1 + 16;   // ch1 <= 79: always offset
        #pragma unroll
        for (int p = 0; p < 4; p++) {
            float lo, hi;
            unpack2(acc2[jp][p], lo, hi);
            g_offset[(size_t)ch1*NVOX + vbase + p] = lo;
            if (ch2 < NOFFCH)
                g_offset[(size_t)ch2*NVOX + vbase + p] = hi;
            else
                g_maskbuf[(size_t)(ch2 - NOFFCH)*NVOX + vbase + p] =
                    1.f / (1.f + __expf(-hi));
        }
    }
    if (cq < 12) {
        #pragma unroll
        for (int p = 0; p < 4; p++)
            g_maskbuf[(size_t)(cq + 96 - NOFFCH)*NVOX + vbase + p] =
                1.f / (1.f + __expf(-acc6[p]));
    }
}

// ---------------------------------------------------------------------------
// Kernel 2: deformable sampling + contraction, offset-prefetch pipelined.
// Phase A: lane = channel, coalesced gathers; offsets read from smem
//   (prefetched one tap ahead, double buffered).
// Phase B: 32o x 32c x 128v tiled GEMM with packed FFMA2.
// ---------------------------------------------------------------------------
#define VB 128
#define VSP 36

__global__ __launch_bounds__(256, 3)
void deform4(const float* __restrict__ b, float* __restrict__ out)
{
    __shared__ float  val_s[VB][VSP];      // 18.4 KB
    __shared__ float  wk_s[CIN*COUT];      // 4 KB
    __shared__ float2 cs[8][32];           // 2 KB
    __shared__ float  offs_s[2][4][VB];    // 4 KB  [par][{z,y,x,m}][vox]

    const int tid  = threadIdx.x;
    const int v0   = blockIdx.x * VB;
    const int warp = tid >> 5;
    const int lane = tid & 31;
    const int j2   = lane >> 3;
    const int c8   = lane & 7;
    const int dz   = c8 >> 2, dy = (c8 >> 1) & 1, dxb = c8 & 1;

    // Phase B role
    const int o0 = (tid & 7) * 4;
    const int vb = (tid >> 3) * 4;

    // Prefetch role: j0 in {0,1}; loads {z,x} or {y,m} for voxel pvi
    const int pvi = tid & 127;
    const int j0  = tid >> 7;
    const int pv  = v0 + pvi;

    ull aL[4], aH[4];
    #pragma unroll
    for (int i = 0; i < 4; i++) { aL[i] = pack2(0.f, 0.f); aH[i] = pack2(0.f, 0.f); }

    // prefetch tap 0
    {
        offs_s[0][j0][pvi] = g_offset[(size_t)(27*j0)*NVOX + pv];
        offs_s[0][j0 + 2][pvi] = (j0 == 0) ? g_offset[(size_t)54*NVOX + pv]
                                           : g_maskbuf[(size_t)0*NVOX + pv];
    }

    #pragma unroll 1
    for (int k = 0; k < KVOL; k++) {
        const int par = k & 1;
        __syncthreads();                 // offs_s[par] ready; prev phase B done

        // weight slice for this tap: [c][o]
        #pragma unroll
        for (int i = 0; i < 4; i++)
            wk_s[tid + 256*i] = g_wt[k*1024 + tid + 256*i];

        // ---- Phase A ----
        const int kz = k / 9, ky = (k / 3) % 3, kx = k % 3;
        #pragma unroll 1
        for (int g = 0; g < 4; g++) {
            const int viL = warp*16 + g*4 + j2;
            const int v   = v0 + viL;
            const int ddv = v >> 12, hhv = (v >> 6) & 63, wxp = v & 63;

            float z  = (float)(ddv - 1 + kz) + offs_s[par][0][viL];
            float y  = (float)(hhv - 1 + ky) + offs_s[par][1][viL];
            float xx = (float)(wxp - 1 + kx) + offs_s[par][2][viL];
            float m  = offs_s[par][3][viL];

            float z0f = floorf(z), y0f = floorf(y), x0f = floorf(xx);
            float zf = z - z0f, yf = y - y0f, xf = xx - x0f;
            int zi = (int)z0f + dz, yi = (int)y0f + dy, xi = (int)x0f + dxb;
            bool valid = (unsigned)zi < (unsigned)DD &&
                         (unsigned)yi < (unsigned)HH &&
                         (unsigned)xi < (unsigned)WW;
            float wg = (dz ? zf : 1.f - zf) * (dy ? yf : 1.f - yf)
                     * (dxb ? xf : 1.f - xf) * m;
            if (!valid) wg = 0.f;
            int zc = min(max(zi, 0), DD-1);
            int yc = min(max(yi, 0), HH-1);
            int xc = min(max(xi, 0), WW-1);
            int idx = (zc*HH + yc)*WW + xc;

            cs[warp][lane] = make_float2(__int_as_float(idx), wg);
            __syncwarp();

            float av[4] = {0.f, 0.f, 0.f, 0.f};
            #pragma unroll
            for (int jj = 0; jj < 4; jj++) {
                #pragma unroll
                for (int ccc = 0; ccc < 8; ccc++) {
                    float2 cd = cs[warp][jj*8 + ccc];
                    av[jj] = fmaf(cd.y,
                                  g_xt[(size_t)__float_as_int(cd.x)*32 + lane],
                                  av[jj]);
                }
            }
            __syncwarp();
            #pragma unroll
            for (int jj = 0; jj < 4; jj++)
                val_s[warp*16 + g*4 + jj][lane] = av[jj];
        }

        // prefetch offsets for next tap into the other buffer (hidden by B)
        if (k + 1 < KVOL) {
            const int kn = k + 1, pn = par ^ 1;
            offs_s[pn][j0][pvi] = g_offset[(size_t)(27*j0 + kn)*NVOX + pv];
            offs_s[pn][j0 + 2][pvi] = (j0 == 0)
                ? g_offset[(size_t)(54 + kn)*NVOX + pv]
                : g_maskbuf[(size_t)kn*NVOX + pv];
        }

        __syncthreads();

        // ---- Phase B: FFMA2-packed 4o x 4v tile over c ----
        #pragma unroll
        for (int c0 = 0; c0 < 8; c0++) {
            float4 xi0 = *(const float4*)&val_s[vb + 0][c0*4];
            float4 xi1 = *(const float4*)&val_s[vb + 1][c0*4];
            float4 xi2 = *(const float4*)&val_s[vb + 2][c0*4];
            float4 xi3 = *(const float4*)&val_s[vb + 3][c0*4];
            #pragma unroll
            for (int ccc = 0; ccc < 4; ccc++) {
                const int c = c0*4 + ccc;
                ull wL = *(const ull*)&wk_s[c*32 + o0];
                ull wH = *(const ull*)&wk_s[c*32 + o0 + 2];
                float x0 = (&xi0.x)[ccc], x1 = (&xi1.x)[ccc];
                float x2 = (&xi2.x)[ccc], x3 = (&xi3.x)[ccc];
                ull xb0 = pack2(x0, x0);
                ull xb1 = pack2(x1, x1);
                ull xb2 = pack2(x2, x2);
                ull xb3 = pack2(x3, x3);
                fma2(aL[0], wL, xb0); fma2(aH[0], wH, xb0);
                fma2(aL[1], wL, xb1); fma2(aH[1], wH, xb1);
                fma2(aL[2], wL, xb2); fma2(aH[2], wH, xb2);
                fma2(aL[3], wL, xb3); fma2(aH[3], wH, xb3);
            }
        }
    }

    // Write-out
    const int vg = v0 + vb;
    float b0 = b[o0], b1 = b[o0+1], b2 = b[o0+2], b3 = b[o0+3];
    #pragma unroll
    for (int i = 0; i < 4; i++) {
        float lo, hi;
        unpack2(aL[i], lo, hi);
        out[(size_t)(o0+0)*NVOX + vg + i] = lo + b0;
        out[(size_t)(o0+1)*NVOX + vg + i] = hi + b1;
        unpack2(aH[i], lo, hi);
        out[(size_t)(o0+2)*NVOX + vg + i] = lo + b2;
        out[(size_t)(o0+3)*NVOX + vg + i] = hi + b3;
    }
}

// ---------------------------------------------------------------------------
// Launch. Inputs: x, w_off, b_off, w_mask, b_mask, w, b
// ---------------------------------------------------------------------------
extern "C" void kernel_launch(void* const* d_in, const int* in_sizes, int n_in,
                              void* d_out, int out_size)
{
    const float* x      = (const float*)d_in[0];
    const float* w_off  = (const float*)d_in[1];
    const float* b_off  = (const float*)d_in[2];
    const float* w_mask = (const float*)d_in[3];
    const float* b_mask = (const float*)d_in[4];
    const float* w      = (const float*)d_in[5];
    const float* b      = (const float*)d_in[6];
    float* out = (float*)d_out;

    cudaFuncSetAttribute(conv_offmask4,
                         cudaFuncAttributeMaxDynamicSharedMemorySize, SMEMC_BYTES);

    prep_wconv<<<(16*16*CC*KVOL + 255)/256, 256>>>(w_off, w_mask);
    transpose_w<<<(KVOL*CIN*COUT)/256, 256>>>(w);
    transpose_x<<<NVOX/32, dim3(32, 8)>>>(x);

    dim3 gc(HH, DD);
    conv_offmask4<<<gc, 256, SMEMC_BYTES>>>(x, b_off, b_mask);

    deform4<<<NVOX/VB, 256>>>(b, out);
}